// round 11
// baseline (speedup 1.0000x reference)
#include <cuda_runtime.h>
#include <cuda_fp16.h>
#include <mma.h>
#include <cstdint>

using namespace nvcuda;

#define N_NODES 100000
#define N_PAD   100096          /* 782 * 128 */
#define N_EDGES 1600000
#define D 128

// ---------------- scratch (device globals; no allocation allowed) ----------------
__device__ int    g_deg[N_NODES];
__device__ int    g_fill[N_NODES];     // running write cursor (init = rowptr)
__device__ int    g_rowptr[N_NODES + 1];
__device__ int    g_csr_src[N_EDGES];
__device__ __align__(16) __half g_xh[(size_t)N_PAD * D];    // x   (fp16)
__device__ __align__(16) __half g_hh[(size_t)N_PAD * D];    // h   (fp16)
__device__ __align__(16) __half g_aggh[(size_t)N_PAD * D];  // agg (fp16)
// weight images: [mat 0..3][K=128][N=128] fp16 row-major
__device__ __align__(16) __half g_Wimg[4][128 * 128];

// ---------------- k_pre: zero deg + weight prep ----------------
#define ZB 391
__global__ void k_pre(const float* __restrict__ W0, const float* __restrict__ W1,
                      const float* __restrict__ W2, const float* __restrict__ W3)
{
    int b = blockIdx.x, tid = threadIdx.x;
    if (b < ZB) {
        int i = b * 256 + tid;
        if (i < N_NODES) g_deg[i] = 0;
    } else {
        int m = b - ZB;
        const float* W = (m == 0) ? W0 : (m == 1) ? W1 : (m == 2) ? W2 : W3;
        __half* hi = &g_Wimg[m][0];
        for (int idx = tid; idx < 128 * 128; idx += 256)
            hi[idx] = __float2half_rn(W[idx]);
    }
}

// ---------------- k_histx: degree histogram || x->fp16 conversion ----------------
#define HB 6250      /* 1.6M edges / 256 */
#define XB 6250      /* 3.2M float4 / 512 */
__global__ void k_histx(const int* __restrict__ ei, const float* __restrict__ x)
{
    int b = blockIdx.x, tid = threadIdx.x;
    if (b < HB) {
        int e = b * 256 + tid;
        atomicAdd(&g_deg[ei[N_EDGES + e]], 1);
    } else {
        int b2 = b - HB;
        const float4* xv = (const float4*)x;
        int f4 = b2 * 512 + tid * 2;
        float4 a = xv[f4], c = xv[f4 + 1];
        __half2 h0 = __floats2half2_rn(a.x, a.y);
        __half2 h1 = __floats2half2_rn(a.z, a.w);
        __half2 h2 = __floats2half2_rn(c.x, c.y);
        __half2 h3 = __floats2half2_rn(c.z, c.w);
        uint4 o;
        o.x = *(uint32_t*)&h0; o.y = *(uint32_t*)&h1;
        o.z = *(uint32_t*)&h2; o.w = *(uint32_t*)&h3;
        *(uint4*)(&g_xh[(size_t)b2 * 2048 + tid * 8]) = o;
    }
}

// ---------------- k_scane: block 0 scans rowptr || other blocks edgecast ----------
__global__ void k_scane(const int* __restrict__ ei, float* __restrict__ outTail)
{
    int t = threadIdx.x;
    if (blockIdx.x == 0) {
        __shared__ int ss[1024];
        const int CH = (N_NODES + 1023) / 1024;
        int b0 = t * CH, b1 = min(b0 + CH, N_NODES);
        int s = 0;
        for (int i = b0; i < b1; i++) s += g_deg[i];
        ss[t] = s; __syncthreads();
        for (int off = 1; off < 1024; off <<= 1) {
            int v = (t >= off) ? ss[t - off] : 0;
            __syncthreads(); ss[t] += v; __syncthreads();
        }
        int excl = (t == 0) ? 0 : ss[t - 1];
        for (int i = b0; i < b1; i++) {
            g_rowptr[i] = excl;
            g_fill[i] = excl;          // write cursor starts at row base
            excl += g_deg[i];
        }
        if (t == 1023) g_rowptr[N_NODES] = excl;
    } else {
        int i = (blockIdx.x - 1) * 4096 + t * 4;
        if (i < 2 * N_EDGES) {
            int4 v = *(const int4*)(ei + i);
            *(float4*)(outTail + i) = make_float4((float)v.x, (float)v.y,
                                                  (float)v.z, (float)v.w);
        }
    }
}

__global__ void k_fill(const int* __restrict__ ei) {
    int e = blockIdx.x * blockDim.x + threadIdx.x;
    if (e < N_EDGES) {
        int dst = ei[N_EDGES + e];
        int slot = atomicAdd(&g_fill[dst], 1);
        g_csr_src[slot] = ei[e];
    }
}

// ---------------- mean aggregation (fp16 in/out), 4-edge MLP, warp/node ----------
// (bit-identical to the 299.6us R8 version)
template <int LAYER>
__global__ void k_agg() {
    const uint2* __restrict__ xin =
        (const uint2*)((LAYER == 1) ? g_xh : g_hh);   // 32 uint2 per row
    int gw = (blockIdx.x * blockDim.x + threadIdx.x) >> 5;
    int lane = threadIdx.x & 31;
    if (gw >= N_NODES) return;
    int e0 = g_rowptr[gw], e1 = g_rowptr[gw + 1];
    float4 a0 = make_float4(0.f, 0.f, 0.f, 0.f);
    float4 a1 = make_float4(0.f, 0.f, 0.f, 0.f);
    int e = e0;
    for (; e + 3 < e1; e += 4) {
        int s0 = g_csr_src[e],     s1 = g_csr_src[e + 1];
        int s2 = g_csr_src[e + 2], s3 = g_csr_src[e + 3];
        uint2 v0 = xin[(size_t)s0 * 32 + lane];
        uint2 v1 = xin[(size_t)s1 * 32 + lane];
        uint2 v2 = xin[(size_t)s2 * 32 + lane];
        uint2 v3 = xin[(size_t)s3 * 32 + lane];
        float2 f;
        f = __half22float2(*(__half2*)&v0.x); a0.x += f.x; a0.y += f.y;
        f = __half22float2(*(__half2*)&v0.y); a0.z += f.x; a0.w += f.y;
        f = __half22float2(*(__half2*)&v1.x); a1.x += f.x; a1.y += f.y;
        f = __half22float2(*(__half2*)&v1.y); a1.z += f.x; a1.w += f.y;
        f = __half22float2(*(__half2*)&v2.x); a0.x += f.x; a0.y += f.y;
        f = __half22float2(*(__half2*)&v2.y); a0.z += f.x; a0.w += f.y;
        f = __half22float2(*(__half2*)&v3.x); a1.x += f.x; a1.y += f.y;
        f = __half22float2(*(__half2*)&v3.y); a1.z += f.x; a1.w += f.y;
    }
    for (; e < e1; e++) {
        int s0 = g_csr_src[e];
        uint2 v0 = xin[(size_t)s0 * 32 + lane];
        float2 f;
        f = __half22float2(*(__half2*)&v0.x); a0.x += f.x; a0.y += f.y;
        f = __half22float2(*(__half2*)&v0.y); a0.z += f.x; a0.w += f.y;
    }
    int d = e1 - e0;
    float di = (d > 0) ? (1.0f / (float)d) : 0.0f;
    __half2 p0 = __floats2half2_rn((a0.x + a1.x) * di, (a0.y + a1.y) * di);
    __half2 p1 = __floats2half2_rn((a0.z + a1.z) * di, (a0.w + a1.w) * di);
    uint2 o;
    o.x = *(uint32_t*)&p0; o.y = *(uint32_t*)&p1;
    *(uint2*)(&g_aggh[(size_t)gw * D + lane * 4]) = o;
}

// ---------------- WMMA fp16 single-term fused SAGE linear ----------------
#define LDA 136
#define LDB 136
#define LDC 132
#define SM_BIAS   (16 * 136 * 4)                 /* 8704 */
#define SM_TILE   (128 * 136 * 2)                /* 34816 */
#define SMEM_REQ  (SM_BIAS + 2 * SM_TILE)        /* 78336 */

template <int LAYER>
__global__ void __launch_bounds__(256, 2) k_wgemm(
    const float* __restrict__ bias,
    float* __restrict__ OutExt)
{
    extern __shared__ char smem[];
    float* bias_rep = (float*)smem;
    __half* As = (__half*)(smem + SM_BIAS);
    __half* Bs = As + 128 * LDA;

    const int tid = threadIdx.x;
    const int wid = tid >> 5;
    const int row0 = blockIdx.x * 128;
    const int wy = wid >> 1;
    const int wx = wid & 1;

    for (int i = tid; i < 16 * 128; i += 256) {
        int r = i >> 7, c = i & 127;
        bias_rep[r * 136 + c] = bias[c];
    }
    __syncthreads();

    wmma::fragment<wmma::accumulator, 16, 16, 16, float> acc[2][4];
#pragma unroll
    for (int i = 0; i < 2; i++)
#pragma unroll
        for (int j = 0; j < 4; j++)
            wmma::load_matrix_sync(acc[i][j], bias_rep + wx * 64 + j * 16, 136,
                                   wmma::mem_row_major);

    const int wl = (LAYER == 1) ? 0 : 2;
#pragma unroll 1
    for (int side = 0; side < 2; side++) {
        if (side == 1) __syncthreads();
        const __half* __restrict__ Asrc =
            (side == 0) ? g_aggh : ((LAYER == 1) ? g_xh : g_hh);
        const uint4* av = (const uint4*)(Asrc + (size_t)row0 * D);
        const uint4* bv = (const uint4*)&g_Wimg[wl + side][0];
#pragma unroll
        for (int it = 0; it < 8; it++) {
            int idx = tid + it * 256;            // 2048 uint4 (8 halves each)
            int m = idx >> 4, c = idx & 15;
            *(uint4*)&As[m * LDA + c * 8] = av[idx];
            *(uint4*)&Bs[m * LDB + c * 8] = bv[idx];
        }
        __syncthreads();

#pragma unroll
        for (int ks = 0; ks < 8; ks++) {
            int k0 = ks * 16;
            wmma::fragment<wmma::matrix_a, 16, 16, 16, __half, wmma::row_major> a[2];
#pragma unroll
            for (int i = 0; i < 2; i++)
                wmma::load_matrix_sync(a[i], As + (wy * 32 + i * 16) * LDA + k0, LDA);
#pragma unroll
            for (int j = 0; j < 4; j++) {
                int n0 = wx * 64 + j * 16;
                wmma::fragment<wmma::matrix_b, 16, 16, 16, __half, wmma::row_major> b;
                wmma::load_matrix_sync(b, Bs + k0 * LDB + n0, LDB);
#pragma unroll
                for (int i = 0; i < 2; i++)
                    wmma::mma_sync(acc[i][j], a[i], b, acc[i][j]);
            }
        }
    }

    // ---- epilogue ----
    if (LAYER == 1) {
#pragma unroll
        for (int i = 0; i < 2; i++)
#pragma unroll
            for (int j = 0; j < 4; j++)
#pragma unroll
                for (int t = 0; t < acc[i][j].num_elements; t++)
                    acc[i][j].x[t] = fmaxf(acc[i][j].x[t], 0.f);
        float* bounce = (float*)smem;
        __syncthreads();
#pragma unroll
        for (int i = 0; i < 2; i++)
#pragma unroll
            for (int j = 0; j < 4; j++)
                wmma::store_matrix_sync(
                    bounce + (size_t)(wy * 32 + i * 16) * LDC + wx * 64 + j * 16,
                    acc[i][j], LDC, wmma::mem_row_major);
        __syncthreads();
        for (int idx = tid; idx < 128 * 32; idx += 256) {
            int r = idx >> 5, q = idx & 31;
            float4 v = *(float4*)&bounce[r * LDC + q * 4];
            __half2 p0 = __floats2half2_rn(v.x, v.y);
            __half2 p1 = __floats2half2_rn(v.z, v.w);
            uint2 hv;
            hv.x = *(uint32_t*)&p0; hv.y = *(uint32_t*)&p1;
            *(uint2*)(&g_hh[(size_t)(row0 + r) * D + q * 4]) = hv;
        }
        return;
    }

    bool direct = (row0 + 128 <= N_NODES);
    if (direct) {
#pragma unroll
        for (int i = 0; i < 2; i++)
#pragma unroll
            for (int j = 0; j < 4; j++)
                wmma::store_matrix_sync(
                    OutExt + (size_t)(row0 + wy * 32 + i * 16) * D + wx * 64 + j * 16,
                    acc[i][j], D, wmma::mem_row_major);
    } else {
        float* bounce = (float*)smem;
        __syncthreads();
#pragma unroll
        for (int i = 0; i < 2; i++)
#pragma unroll
            for (int j = 0; j < 4; j++)
                wmma::store_matrix_sync(
                    bounce + (size_t)(wy * 32 + i * 16) * LDC + wx * 64 + j * 16,
                    acc[i][j], LDC, wmma::mem_row_major);
        __syncthreads();
        int valid = N_NODES - row0;
        for (int idx = tid; idx < valid * 32; idx += 256) {
            int r = idx >> 5, q = idx & 31;
            float4 v = *(float4*)&bounce[r * LDC + q * 4];
            *(float4*)(OutExt + (size_t)(row0 + r) * D + q * 4) = v;
        }
    }
}

// ---------------- launch ----------------
extern "C" void kernel_launch(void* const* d_in, const int* in_sizes, int n_in,
                              void* d_out, int out_size)
{
    const float* x   = (const float*)d_in[0];
    const float* W1l = (const float*)d_in[1];
    const float* b1  = (const float*)d_in[2];
    const float* W1r = (const float*)d_in[3];
    const float* W2l = (const float*)d_in[4];
    const float* b2  = (const float*)d_in[5];
    const float* W2r = (const float*)d_in[6];
    const int*   ei  = (const int*)d_in[7];
    float* out = (float*)d_out;

    const int TB = 256;
    cudaFuncSetAttribute(k_wgemm<1>, cudaFuncAttributeMaxDynamicSharedMemorySize, SMEM_REQ);
    cudaFuncSetAttribute(k_wgemm<2>, cudaFuncAttributeMaxDynamicSharedMemorySize, SMEM_REQ);

    const int aggBlocks  = (N_NODES * 32 + TB - 1) / TB;
    const int gemmBlocks = (N_NODES + 127) / 128;   // 782
    const int ecBlocks   = (2 * N_EDGES + 4095) / 4096 + 1;  // 782 (incl. scan block)

    k_pre<<<ZB + 4, TB>>>(W1l, W1r, W2l, W2r);
    k_histx<<<HB + XB, TB>>>(ei, x);
    k_scane<<<ecBlocks, 1024>>>(ei, out + (size_t)N_NODES * D);
    k_fill<<<(N_EDGES + TB - 1) / TB, TB>>>(ei);

    k_agg<1><<<aggBlocks, TB>>>();
    k_wgemm<1><<<gemmBlocks, TB, SMEM_REQ>>>(b1, nullptr);

    k_agg<2><<<aggBlocks, TB>>>();
    k_wgemm<2><<<gemmBlocks, TB, SMEM_REQ>>>(b2, out);
}

// round 12
// speedup vs baseline: 1.0087x; 1.0087x over previous
#include <cuda_runtime.h>
#include <cuda_fp16.h>
#include <mma.h>
#include <cstdint>

using namespace nvcuda;

#define N_NODES 100000
#define N_PAD   100096          /* 782 * 128 */
#define N_EDGES 1600000
#define D 128

// ---------------- scratch (device globals; no allocation allowed) ----------------
__device__ int    g_deg[N_NODES];
__device__ int    g_fill[N_NODES];
__device__ int    g_rowptr[N_NODES + 1];
__device__ int    g_csr_src[N_EDGES];
__device__ __align__(16) __half g_xh[(size_t)N_PAD * D];    // x   (fp16)
__device__ __align__(16) __half g_hh[(size_t)N_PAD * D];    // h   (fp16)
__device__ __align__(16) __half g_aggh[(size_t)N_PAD * D];  // agg (fp16)
// weight images: [mat 0..3][K=128][N=128] fp16 row-major
__device__ __align__(16) __half g_Wimg[4][128 * 128];

// ---------------- mega-init: zero deg + weight prep + edgecast + x->fp16 ----------
#define ZB 391
#define WB 4
#define EB 3125     /* 3.2M floats / 1024 per block */
#define XB 6250     /* 12.8M floats / 2048 per block */

__global__ void k_init(const float* __restrict__ x,
                       const float* __restrict__ W0, const float* __restrict__ W1,
                       const float* __restrict__ W2, const float* __restrict__ W3,
                       const int* __restrict__ ei, float* __restrict__ outTail)
{
    int b = blockIdx.x;
    int tid = threadIdx.x;
    if (b < ZB) {
        int i = b * 256 + tid;
        if (i < N_NODES) g_deg[i] = 0;
    } else if (b < ZB + WB) {
        int m = b - ZB;
        const float* W = (m == 0) ? W0 : (m == 1) ? W1 : (m == 2) ? W2 : W3;
        __half* hi = &g_Wimg[m][0];
        for (int idx = tid; idx < 128 * 128; idx += 256)
            hi[idx] = __float2half_rn(W[idx]);
    } else if (b < ZB + WB + EB) {
        int i = (b - ZB - WB) * 1024 + tid * 4;
        int4 v = *(const int4*)(ei + i);
        *(float4*)(outTail + i) = make_float4((float)v.x, (float)v.y,
                                              (float)v.z, (float)v.w);
    } else {
        int b2 = b - ZB - WB - EB;
        const float4* xv = (const float4*)x;
        int f4 = b2 * 512 + tid * 2;
        float4 a = xv[f4], c = xv[f4 + 1];
        __half2 h0 = __floats2half2_rn(a.x, a.y);
        __half2 h1 = __floats2half2_rn(a.z, a.w);
        __half2 h2 = __floats2half2_rn(c.x, c.y);
        __half2 h3 = __floats2half2_rn(c.z, c.w);
        uint4 o;
        o.x = *(uint32_t*)&h0; o.y = *(uint32_t*)&h1;
        o.z = *(uint32_t*)&h2; o.w = *(uint32_t*)&h3;
        *(uint4*)(&g_xh[(size_t)b2 * 2048 + tid * 8]) = o;
    }
}

// ---------------- CSR build ----------------
__global__ void k_hist(const int* __restrict__ ei) {
    int e = blockIdx.x * blockDim.x + threadIdx.x;
    if (e < N_EDGES) atomicAdd(&g_deg[ei[N_EDGES + e]], 1);
}
__global__ void k_scan() {
    __shared__ int ss[1024];
    int t = threadIdx.x;
    const int CH = (N_NODES + 1023) / 1024;
    int b0 = t * CH, b1 = min(b0 + CH, N_NODES);
    int s = 0;
    for (int i = b0; i < b1; i++) { s += g_deg[i]; g_fill[i] = 0; }
    ss[t] = s; __syncthreads();
    for (int off = 1; off < 1024; off <<= 1) {
        int v = (t >= off) ? ss[t - off] : 0;
        __syncthreads(); ss[t] += v; __syncthreads();
    }
    int excl = (t == 0) ? 0 : ss[t - 1];
    for (int i = b0; i < b1; i++) { g_rowptr[i] = excl; excl += g_deg[i]; }
    if (t == 1023) g_rowptr[N_NODES] = excl;
}
__global__ void k_fill(const int* __restrict__ ei) {
    int e = blockIdx.x * blockDim.x + threadIdx.x;
    if (e < N_EDGES) {
        int dst = ei[N_EDGES + e];
        int p = atomicAdd(&g_fill[dst], 1);
        g_csr_src[g_rowptr[dst] + p] = ei[e];
    }
}

// ---------------- mean aggregation (fp16 in/out), 4-edge MLP, warp/node ----------
template <int LAYER>
__global__ void k_agg() {
    const uint2* __restrict__ xin =
        (const uint2*)((LAYER == 1) ? g_xh : g_hh);   // 32 uint2 per row
    int gw = (blockIdx.x * blockDim.x + threadIdx.x) >> 5;
    int lane = threadIdx.x & 31;
    if (gw >= N_NODES) return;
    int e0 = g_rowptr[gw], e1 = g_rowptr[gw + 1];
    float4 a0 = make_float4(0.f, 0.f, 0.f, 0.f);
    float4 a1 = make_float4(0.f, 0.f, 0.f, 0.f);
    int e = e0;
    for (; e + 3 < e1; e += 4) {
        int s0 = g_csr_src[e],     s1 = g_csr_src[e + 1];
        int s2 = g_csr_src[e + 2], s3 = g_csr_src[e + 3];
        uint2 v0 = xin[(size_t)s0 * 32 + lane];
        uint2 v1 = xin[(size_t)s1 * 32 + lane];
        uint2 v2 = xin[(size_t)s2 * 32 + lane];
        uint2 v3 = xin[(size_t)s3 * 32 + lane];
        float2 f;
        f = __half22float2(*(__half2*)&v0.x); a0.x += f.x; a0.y += f.y;
        f = __half22float2(*(__half2*)&v0.y); a0.z += f.x; a0.w += f.y;
        f = __half22float2(*(__half2*)&v1.x); a1.x += f.x; a1.y += f.y;
        f = __half22float2(*(__half2*)&v1.y); a1.z += f.x; a1.w += f.y;
        f = __half22float2(*(__half2*)&v2.x); a0.x += f.x; a0.y += f.y;
        f = __half22float2(*(__half2*)&v2.y); a0.z += f.x; a0.w += f.y;
        f = __half22float2(*(__half2*)&v3.x); a1.x += f.x; a1.y += f.y;
        f = __half22float2(*(__half2*)&v3.y); a1.z += f.x; a1.w += f.y;
    }
    for (; e < e1; e++) {
        int s0 = g_csr_src[e];
        uint2 v0 = xin[(size_t)s0 * 32 + lane];
        float2 f;
        f = __half22float2(*(__half2*)&v0.x); a0.x += f.x; a0.y += f.y;
        f = __half22float2(*(__half2*)&v0.y); a0.z += f.x; a0.w += f.y;
    }
    int d = e1 - e0;
    float di = (d > 0) ? (1.0f / (float)d) : 0.0f;
    __half2 p0 = __floats2half2_rn((a0.x + a1.x) * di, (a0.y + a1.y) * di);
    __half2 p1 = __floats2half2_rn((a0.z + a1.z) * di, (a0.w + a1.w) * di);
    uint2 o;
    o.x = *(uint32_t*)&p0; o.y = *(uint32_t*)&p1;
    *(uint2*)(&g_aggh[(size_t)gw * D + lane * 4]) = o;
}

// ---------------- WMMA fp16 single-term fused SAGE linear ----------------
// out[128x128] = agg@Wl + root@Wr + bias (+ReLU layer1); A,B plain fp16.
#define LDA 136
#define LDB 136
#define LDC 132
#define SM_BIAS   (16 * 136 * 4)                 /* 8704 */
#define SM_TILE   (128 * 136 * 2)                /* 34816 */
#define SMEM_REQ  (SM_BIAS + 2 * SM_TILE)        /* 78336 */

template <int LAYER>
__global__ void __launch_bounds__(256, 2) k_wgemm(
    const float* __restrict__ bias,
    float* __restrict__ OutExt)
{
    extern __shared__ char smem[];
    float* bias_rep = (float*)smem;
    __half* As = (__half*)(smem + SM_BIAS);
    __half* Bs = As + 128 * LDA;

    const int tid = threadIdx.x;
    const int wid = tid >> 5;
    const int row0 = blockIdx.x * 128;
    const int wy = wid >> 1;
    const int wx = wid & 1;

    for (int i = tid; i < 16 * 128; i += 256) {
        int r = i >> 7, c = i & 127;
        bias_rep[r * 136 + c] = bias[c];
    }
    __syncthreads();

    wmma::fragment<wmma::accumulator, 16, 16, 16, float> acc[2][4];
#pragma unroll
    for (int i = 0; i < 2; i++)
#pragma unroll
        for (int j = 0; j < 4; j++)
            wmma::load_matrix_sync(acc[i][j], bias_rep + wx * 64 + j * 16, 136,
                                   wmma::mem_row_major);

    const int wl = (LAYER == 1) ? 0 : 2;
#pragma unroll 1
    for (int side = 0; side < 2; side++) {
        if (side == 1) __syncthreads();
        const __half* __restrict__ Asrc =
            (side == 0) ? g_aggh : ((LAYER == 1) ? g_xh : g_hh);
        const uint4* av = (const uint4*)(Asrc + (size_t)row0 * D);
        const uint4* bv = (const uint4*)&g_Wimg[wl + side][0];
#pragma unroll
        for (int it = 0; it < 8; it++) {
            int idx = tid + it * 256;            // 2048 uint4 (8 halves each)
            int m = idx >> 4, c = idx & 15;
            *(uint4*)&As[m * LDA + c * 8] = av[idx];
            *(uint4*)&Bs[m * LDB + c * 8] = bv[idx];
        }
        __syncthreads();

#pragma unroll
        for (int ks = 0; ks < 8; ks++) {
            int k0 = ks * 16;
            wmma::fragment<wmma::matrix_a, 16, 16, 16, __half, wmma::row_major> a[2];
#pragma unroll
            for (int i = 0; i < 2; i++)
                wmma::load_matrix_sync(a[i], As + (wy * 32 + i * 16) * LDA + k0, LDA);
#pragma unroll
            for (int j = 0; j < 4; j++) {
                int n0 = wx * 64 + j * 16;
                wmma::fragment<wmma::matrix_b, 16, 16, 16, __half, wmma::row_major> b;
                wmma::load_matrix_sync(b, Bs + k0 * LDB + n0, LDB);
#pragma unroll
                for (int i = 0; i < 2; i++)
                    wmma::mma_sync(acc[i][j], a[i], b, acc[i][j]);
            }
        }
    }

    // ---- epilogue ----
    if (LAYER == 1) {
#pragma unroll
        for (int i = 0; i < 2; i++)
#pragma unroll
            for (int j = 0; j < 4; j++)
#pragma unroll
                for (int t = 0; t < acc[i][j].num_elements; t++)
                    acc[i][j].x[t] = fmaxf(acc[i][j].x[t], 0.f);
        float* bounce = (float*)smem;
        __syncthreads();
#pragma unroll
        for (int i = 0; i < 2; i++)
#pragma unroll
            for (int j = 0; j < 4; j++)
                wmma::store_matrix_sync(
                    bounce + (size_t)(wy * 32 + i * 16) * LDC + wx * 64 + j * 16,
                    acc[i][j], LDC, wmma::mem_row_major);
        __syncthreads();
        for (int idx = tid; idx < 128 * 32; idx += 256) {
            int r = idx >> 5, q = idx & 31;
            float4 v = *(float4*)&bounce[r * LDC + q * 4];
            __half2 p0 = __floats2half2_rn(v.x, v.y);
            __half2 p1 = __floats2half2_rn(v.z, v.w);
            uint2 hv;
            hv.x = *(uint32_t*)&p0; hv.y = *(uint32_t*)&p1;
            *(uint2*)(&g_hh[(size_t)(row0 + r) * D + q * 4]) = hv;
        }
        return;
    }

    bool direct = (row0 + 128 <= N_NODES);
    if (direct) {
#pragma unroll
        for (int i = 0; i < 2; i++)
#pragma unroll
            for (int j = 0; j < 4; j++)
                wmma::store_matrix_sync(
                    OutExt + (size_t)(row0 + wy * 32 + i * 16) * D + wx * 64 + j * 16,
                    acc[i][j], D, wmma::mem_row_major);
    } else {
        float* bounce = (float*)smem;
        __syncthreads();
#pragma unroll
        for (int i = 0; i < 2; i++)
#pragma unroll
            for (int j = 0; j < 4; j++)
                wmma::store_matrix_sync(
                    bounce + (size_t)(wy * 32 + i * 16) * LDC + wx * 64 + j * 16,
                    acc[i][j], LDC, wmma::mem_row_major);
        __syncthreads();
        int valid = N_NODES - row0;
        for (int idx = tid; idx < valid * 32; idx += 256) {
            int r = idx >> 5, q = idx & 31;
            float4 v = *(float4*)&bounce[r * LDC + q * 4];
            *(float4*)(OutExt + (size_t)(row0 + r) * D + q * 4) = v;
        }
    }
}

// ---------------- launch ----------------
extern "C" void kernel_launch(void* const* d_in, const int* in_sizes, int n_in,
                              void* d_out, int out_size)
{
    const float* x   = (const float*)d_in[0];
    const float* W1l = (const float*)d_in[1];
    const float* b1  = (const float*)d_in[2];
    const float* W1r = (const float*)d_in[3];
    const float* W2l = (const float*)d_in[4];
    const float* b2  = (const float*)d_in[5];
    const float* W2r = (const float*)d_in[6];
    const int*   ei  = (const int*)d_in[7];
    float* out = (float*)d_out;

    const int TB = 256;
    cudaFuncSetAttribute(k_wgemm<1>, cudaFuncAttributeMaxDynamicSharedMemorySize, SMEM_REQ);
    cudaFuncSetAttribute(k_wgemm<2>, cudaFuncAttributeMaxDynamicSharedMemorySize, SMEM_REQ);

    const int aggBlocks  = (N_NODES * 32 + TB - 1) / TB;
    const int gemmBlocks = (N_NODES + 127) / 128;   // 782

    k_init<<<ZB + WB + EB + XB, TB>>>(x, W1l, W1r, W2l, W2r, ei,
                                      out + (size_t)N_NODES * D);
    k_hist<<<(N_EDGES + TB - 1) / TB, TB>>>(ei);
    k_scan<<<1, 1024>>>();
    k_fill<<<(N_EDGES + TB - 1) / TB, TB>>>(ei);

    k_agg<1><<<aggBlocks, TB>>>();
    k_wgemm<1><<<gemmBlocks, TB, SMEM_REQ>>>(b1, nullptr);

    k_agg<2><<<aggBlocks, TB>>>();
    k_wgemm<2><<<gemmBlocks, TB, SMEM_REQ>>>(b2, out);
}

// round 13
// speedup vs baseline: 1.2079x; 1.1975x over previous
#include <cuda_runtime.h>
#include <cuda_fp16.h>
#include <mma.h>
#include <cstdint>

using namespace nvcuda;

#define N_NODES 100000
#define N_PAD   100096          /* 782 * 128 */
#define N_EDGES 1600000
#define D 128

// ---------------- scratch (device globals; no allocation allowed) ----------------
__device__ int    g_deg[N_NODES];
__device__ int    g_fill[N_NODES];
__device__ int    g_rowptr[N_NODES + 1];
__device__ int    g_csr_src[N_EDGES];
__device__ __align__(16) __half g_xh[(size_t)N_PAD * D];    // x   (fp16)
__device__ __align__(16) __half g_hh[(size_t)N_PAD * D];    // h   (fp16)
__device__ __align__(16) __half g_aggh[(size_t)N_PAD * D];  // agg (fp16)
// weight images: [mat 0..3][K=128][N=128] fp16 row-major
__device__ __align__(16) __half g_Wimg[4][128 * 128];

// ---------------- front-end kernels (split for multi-stream overlap) --------------
__global__ void k_zero() {
    int i = blockIdx.x * blockDim.x + threadIdx.x;
    if (i < N_NODES) { g_deg[i] = 0; g_fill[i] = 0; }
}

__global__ void k_wprep(const float* __restrict__ W0, const float* __restrict__ W1,
                        const float* __restrict__ W2, const float* __restrict__ W3)
{
    int m = blockIdx.x, tid = threadIdx.x;
    const float* W = (m == 0) ? W0 : (m == 1) ? W1 : (m == 2) ? W2 : W3;
    __half* hi = &g_Wimg[m][0];
    for (int idx = tid; idx < 128 * 128; idx += 256)
        hi[idx] = __float2half_rn(W[idx]);
}

__global__ void k_xconv(const float* __restrict__ x) {
    const float4* xv = (const float4*)x;
    int f4 = blockIdx.x * 512 + threadIdx.x * 2;
    float4 a = xv[f4], c = xv[f4 + 1];
    __half2 h0 = __floats2half2_rn(a.x, a.y);
    __half2 h1 = __floats2half2_rn(a.z, a.w);
    __half2 h2 = __floats2half2_rn(c.x, c.y);
    __half2 h3 = __floats2half2_rn(c.z, c.w);
    uint4 o;
    o.x = *(uint32_t*)&h0; o.y = *(uint32_t*)&h1;
    o.z = *(uint32_t*)&h2; o.w = *(uint32_t*)&h3;
    *(uint4*)(&g_xh[(size_t)blockIdx.x * 2048 + threadIdx.x * 8]) = o;
}

__global__ void k_edgecast(const int* __restrict__ ei, float* __restrict__ outTail) {
    int i = blockIdx.x * 4096 + threadIdx.x * 4;
    if (i < 2 * N_EDGES) {
        int4 v = *(const int4*)(ei + i);
        *(float4*)(outTail + i) = make_float4((float)v.x, (float)v.y,
                                              (float)v.z, (float)v.w);
    }
}

// ---------------- CSR build ----------------
__global__ void k_hist(const int* __restrict__ ei) {
    int e = blockIdx.x * blockDim.x + threadIdx.x;
    if (e < N_EDGES) atomicAdd(&g_deg[ei[N_EDGES + e]], 1);
}
__global__ void k_scan() {
    __shared__ int ss[1024];
    int t = threadIdx.x;
    const int CH = (N_NODES + 1023) / 1024;
    int b0 = t * CH, b1 = min(b0 + CH, N_NODES);
    int s = 0;
    for (int i = b0; i < b1; i++) s += g_deg[i];
    ss[t] = s; __syncthreads();
    for (int off = 1; off < 1024; off <<= 1) {
        int v = (t >= off) ? ss[t - off] : 0;
        __syncthreads(); ss[t] += v; __syncthreads();
    }
    int excl = (t == 0) ? 0 : ss[t - 1];
    for (int i = b0; i < b1; i++) { g_rowptr[i] = excl; excl += g_deg[i]; }
    if (t == 1023) g_rowptr[N_NODES] = excl;
}
__global__ void k_fill(const int* __restrict__ ei) {
    int e = (blockIdx.x * blockDim.x + threadIdx.x) * 2;
    if (e < N_EDGES) {
        int dst0 = ei[N_EDGES + e];
        int src0 = ei[e];
        int dst1 = (e + 1 < N_EDGES) ? ei[N_EDGES + e + 1] : -1;
        int src1 = (e + 1 < N_EDGES) ? ei[e + 1] : 0;
        int p0 = atomicAdd(&g_fill[dst0], 1);
        g_csr_src[g_rowptr[dst0] + p0] = src0;
        if (dst1 >= 0) {
            int p1 = atomicAdd(&g_fill[dst1], 1);
            g_csr_src[g_rowptr[dst1] + p1] = src1;
        }
    }
}

// ---------------- mean aggregation (fp16 in/out), 4-edge MLP, warp/node ----------
template <int LAYER>
__global__ void k_agg() {
    const uint2* __restrict__ xin =
        (const uint2*)((LAYER == 1) ? g_xh : g_hh);   // 32 uint2 per row
    int gw = (blockIdx.x * blockDim.x + threadIdx.x) >> 5;
    int lane = threadIdx.x & 31;
    if (gw >= N_NODES) return;
    int e0 = g_rowptr[gw], e1 = g_rowptr[gw + 1];
    float4 a0 = make_float4(0.f, 0.f, 0.f, 0.f);
    float4 a1 = make_float4(0.f, 0.f, 0.f, 0.f);
    int e = e0;
    for (; e + 3 < e1; e += 4) {
        int s0 = g_csr_src[e],     s1 = g_csr_src[e + 1];
        int s2 = g_csr_src[e + 2], s3 = g_csr_src[e + 3];
        uint2 v0 = xin[(size_t)s0 * 32 + lane];
        uint2 v1 = xin[(size_t)s1 * 32 + lane];
        uint2 v2 = xin[(size_t)s2 * 32 + lane];
        uint2 v3 = xin[(size_t)s3 * 32 + lane];
        float2 f;
        f = __half22float2(*(__half2*)&v0.x); a0.x += f.x; a0.y += f.y;
        f = __half22float2(*(__half2*)&v0.y); a0.z += f.x; a0.w += f.y;
        f = __half22float2(*(__half2*)&v1.x); a1.x += f.x; a1.y += f.y;
        f = __half22float2(*(__half2*)&v1.y); a1.z += f.x; a1.w += f.y;
        f = __half22float2(*(__half2*)&v2.x); a0.x += f.x; a0.y += f.y;
        f = __half22float2(*(__half2*)&v2.y); a0.z += f.x; a0.w += f.y;
        f = __half22float2(*(__half2*)&v3.x); a1.x += f.x; a1.y += f.y;
        f = __half22float2(*(__half2*)&v3.y); a1.z += f.x; a1.w += f.y;
    }
    for (; e < e1; e++) {
        int s0 = g_csr_src[e];
        uint2 v0 = xin[(size_t)s0 * 32 + lane];
        float2 f;
        f = __half22float2(*(__half2*)&v0.x); a0.x += f.x; a0.y += f.y;
        f = __half22float2(*(__half2*)&v0.y); a0.z += f.x; a0.w += f.y;
    }
    int d = e1 - e0;
    float di = (d > 0) ? (1.0f / (float)d) : 0.0f;
    __half2 p0 = __floats2half2_rn((a0.x + a1.x) * di, (a0.y + a1.y) * di);
    __half2 p1 = __floats2half2_rn((a0.z + a1.z) * di, (a0.w + a1.w) * di);
    uint2 o;
    o.x = *(uint32_t*)&p0; o.y = *(uint32_t*)&p1;
    *(uint2*)(&g_aggh[(size_t)gw * D + lane * 4]) = o;
}

// ---------------- WMMA fp16 single-term fused SAGE linear ----------------
// out[128x128] = agg@Wl + root@Wr + bias (+ReLU layer1); A,B plain fp16.
#define LDA 136
#define LDB 136
#define LDC 132
#define SM_BIAS   (16 * 136 * 4)                 /* 8704 */
#define SM_TILE   (128 * 136 * 2)                /* 34816 */
#define SMEM_REQ  (SM_BIAS + 2 * SM_TILE)        /* 78336 */

template <int LAYER>
__global__ void __launch_bounds__(256, 2) k_wgemm(
    const float* __restrict__ bias,
    float* __restrict__ OutExt)
{
    extern __shared__ char smem[];
    float* bias_rep = (float*)smem;
    __half* As = (__half*)(smem + SM_BIAS);
    __half* Bs = As + 128 * LDA;

    const int tid = threadIdx.x;
    const int wid = tid >> 5;
    const int row0 = blockIdx.x * 128;
    const int wy = wid >> 1;
    const int wx = wid & 1;

    for (int i = tid; i < 16 * 128; i += 256) {
        int r = i >> 7, c = i & 127;
        bias_rep[r * 136 + c] = bias[c];
    }
    __syncthreads();

    wmma::fragment<wmma::accumulator, 16, 16, 16, float> acc[2][4];
#pragma unroll
    for (int i = 0; i < 2; i++)
#pragma unroll
        for (int j = 0; j < 4; j++)
            wmma::load_matrix_sync(acc[i][j], bias_rep + wx * 64 + j * 16, 136,
                                   wmma::mem_row_major);

    const int wl = (LAYER == 1) ? 0 : 2;
#pragma unroll 1
    for (int side = 0; side < 2; side++) {
        if (side == 1) __syncthreads();
        const __half* __restrict__ Asrc =
            (side == 0) ? g_aggh : ((LAYER == 1) ? g_xh : g_hh);
        const uint4* av = (const uint4*)(Asrc + (size_t)row0 * D);
        const uint4* bv = (const uint4*)&g_Wimg[wl + side][0];
#pragma unroll
        for (int it = 0; it < 8; it++) {
            int idx = tid + it * 256;            // 2048 uint4 (8 halves each)
            int m = idx >> 4, c = idx & 15;
            *(uint4*)&As[m * LDA + c * 8] = av[idx];
            *(uint4*)&Bs[m * LDB + c * 8] = bv[idx];
        }
        __syncthreads();

#pragma unroll
        for (int ks = 0; ks < 8; ks++) {
            int k0 = ks * 16;
            wmma::fragment<wmma::matrix_a, 16, 16, 16, __half, wmma::row_major> a[2];
#pragma unroll
            for (int i = 0; i < 2; i++)
                wmma::load_matrix_sync(a[i], As + (wy * 32 + i * 16) * LDA + k0, LDA);
#pragma unroll
            for (int j = 0; j < 4; j++) {
                int n0 = wx * 64 + j * 16;
                wmma::fragment<wmma::matrix_b, 16, 16, 16, __half, wmma::row_major> b;
                wmma::load_matrix_sync(b, Bs + k0 * LDB + n0, LDB);
#pragma unroll
                for (int i = 0; i < 2; i++)
                    wmma::mma_sync(acc[i][j], a[i], b, acc[i][j]);
            }
        }
    }

    // ---- epilogue ----
    if (LAYER == 1) {
#pragma unroll
        for (int i = 0; i < 2; i++)
#pragma unroll
            for (int j = 0; j < 4; j++)
#pragma unroll
                for (int t = 0; t < acc[i][j].num_elements; t++)
                    acc[i][j].x[t] = fmaxf(acc[i][j].x[t], 0.f);
        float* bounce = (float*)smem;
        __syncthreads();
#pragma unroll
        for (int i = 0; i < 2; i++)
#pragma unroll
            for (int j = 0; j < 4; j++)
                wmma::store_matrix_sync(
                    bounce + (size_t)(wy * 32 + i * 16) * LDC + wx * 64 + j * 16,
                    acc[i][j], LDC, wmma::mem_row_major);
        __syncthreads();
        for (int idx = tid; idx < 128 * 32; idx += 256) {
            int r = idx >> 5, q = idx & 31;
            float4 v = *(float4*)&bounce[r * LDC + q * 4];
            __half2 p0 = __floats2half2_rn(v.x, v.y);
            __half2 p1 = __floats2half2_rn(v.z, v.w);
            uint2 hv;
            hv.x = *(uint32_t*)&p0; hv.y = *(uint32_t*)&p1;
            *(uint2*)(&g_hh[(size_t)(row0 + r) * D + q * 4]) = hv;
        }
        return;
    }

    bool direct = (row0 + 128 <= N_NODES);
    if (direct) {
#pragma unroll
        for (int i = 0; i < 2; i++)
#pragma unroll
            for (int j = 0; j < 4; j++)
                wmma::store_matrix_sync(
                    OutExt + (size_t)(row0 + wy * 32 + i * 16) * D + wx * 64 + j * 16,
                    acc[i][j], D, wmma::mem_row_major);
    } else {
        float* bounce = (float*)smem;
        __syncthreads();
#pragma unroll
        for (int i = 0; i < 2; i++)
#pragma unroll
            for (int j = 0; j < 4; j++)
                wmma::store_matrix_sync(
                    bounce + (size_t)(wy * 32 + i * 16) * LDC + wx * 64 + j * 16,
                    acc[i][j], LDC, wmma::mem_row_major);
        __syncthreads();
        int valid = N_NODES - row0;
        for (int idx = tid; idx < valid * 32; idx += 256) {
            int r = idx >> 5, q = idx & 31;
            float4 v = *(float4*)&bounce[r * LDC + q * 4];
            *(float4*)(OutExt + (size_t)(row0 + r) * D + q * 4) = v;
        }
    }
}

// ---------------- launch (3 parallel graph branches) ----------------
extern "C" void kernel_launch(void* const* d_in, const int* in_sizes, int n_in,
                              void* d_out, int out_size)
{
    const float* x   = (const float*)d_in[0];
    const float* W1l = (const float*)d_in[1];
    const float* b1  = (const float*)d_in[2];
    const float* W1r = (const float*)d_in[3];
    const float* W2l = (const float*)d_in[4];
    const float* b2  = (const float*)d_in[5];
    const float* W2r = (const float*)d_in[6];
    const int*   ei  = (const int*)d_in[7];
    float* out = (float*)d_out;

    static cudaStream_t s1 = nullptr, s2 = nullptr;
    static cudaEvent_t evRoot = nullptr, evPrep = nullptr, evEdge = nullptr;
    if (!s1) {
        cudaStreamCreateWithFlags(&s1, cudaStreamNonBlocking);
        cudaStreamCreateWithFlags(&s2, cudaStreamNonBlocking);
        cudaEventCreateWithFlags(&evRoot, cudaEventDisableTiming);
        cudaEventCreateWithFlags(&evPrep, cudaEventDisableTiming);
        cudaEventCreateWithFlags(&evEdge, cudaEventDisableTiming);
        cudaFuncSetAttribute(k_wgemm<1>, cudaFuncAttributeMaxDynamicSharedMemorySize, SMEM_REQ);
        cudaFuncSetAttribute(k_wgemm<2>, cudaFuncAttributeMaxDynamicSharedMemorySize, SMEM_REQ);
    }

    const int TB = 256;
    const int aggBlocks  = (N_NODES * 32 + TB - 1) / TB;
    const int gemmBlocks = (N_NODES + 127) / 128;   // 782

    // fork
    cudaEventRecord(evRoot, 0);
    cudaStreamWaitEvent(s1, evRoot, 0);
    cudaStreamWaitEvent(s2, evRoot, 0);

    // branch s1: weight prep + x->fp16 (needed by agg1/gemm1)
    k_wprep<<<4, TB, 0, s1>>>(W1l, W1r, W2l, W2r);
    k_xconv<<<6250, TB, 0, s1>>>(x);
    cudaEventRecord(evPrep, s1);

    // branch s2: edge_index passthrough cast (independent)
    k_edgecast<<<782, 1024, 0, s2>>>(ei, out + (size_t)N_NODES * D);
    cudaEventRecord(evEdge, s2);

    // branch s0: CSR build chain
    k_zero<<<(N_NODES + TB - 1) / TB, TB>>>();
    k_hist<<<(N_EDGES + TB - 1) / TB, TB>>>(ei);
    k_scan<<<1, 1024>>>();
    k_fill<<<(N_EDGES / 2 + TB - 1) / TB, TB>>>(ei);

    // join prep branch, then compute
    cudaStreamWaitEvent(0, evPrep, 0);
    k_agg<1><<<aggBlocks, TB>>>();
    k_wgemm<1><<<gemmBlocks, TB, SMEM_REQ>>>(b1, nullptr);
    k_agg<2><<<aggBlocks, TB>>>();
    k_wgemm<2><<<gemmBlocks, TB, SMEM_REQ>>>(b2, out);

    // join edgecast branch
    cudaStreamWaitEvent(0, evEdge, 0);
}

// round 14
// speedup vs baseline: 1.2509x; 1.0356x over previous
#include <cuda_runtime.h>
#include <cuda_fp16.h>
#include <mma.h>
#include <cstdint>

using namespace nvcuda;

#define N_NODES 100000
#define N_PAD   100096          /* 782 * 128 */
#define N_EDGES 1600000
#define D 128

// ---------------- scratch (device globals; no allocation allowed) ----------------
__device__ int    g_deg[N_NODES];
__device__ int    g_fill[N_NODES];
__device__ int    g_rowptr[N_NODES + 1];
__device__ int    g_csr_src[N_EDGES];
__device__ __align__(16) __half g_xh[(size_t)N_PAD * D];    // x   (fp16)
__device__ __align__(16) __half g_hh[(size_t)N_PAD * D];    // h   (fp16)
__device__ __align__(16) __half g_aggh[(size_t)N_PAD * D];  // agg (fp16)
// weight images: [mat 0..3][K=128][N=128] fp16 row-major
__device__ __align__(16) __half g_Wimg[4][128 * 128];

// ---------------- front-end kernels (split for multi-stream overlap) --------------
__global__ void k_zero() {
    int i = blockIdx.x * blockDim.x + threadIdx.x;
    if (i < N_NODES) { g_deg[i] = 0; g_fill[i] = 0; }
}

__global__ void k_wprep(const float* __restrict__ W0, const float* __restrict__ W1,
                        const float* __restrict__ W2, const float* __restrict__ W3)
{
    int m = blockIdx.x, tid = threadIdx.x;
    const float* W = (m == 0) ? W0 : (m == 1) ? W1 : (m == 2) ? W2 : W3;
    __half* hi = &g_Wimg[m][0];
    for (int idx = tid; idx < 128 * 128; idx += 256)
        hi[idx] = __float2half_rn(W[idx]);
}

__global__ void k_xconv(const float* __restrict__ x) {
    const float4* xv = (const float4*)x;
    int f4 = blockIdx.x * 512 + threadIdx.x * 2;
    float4 a = xv[f4], c = xv[f4 + 1];
    __half2 h0 = __floats2half2_rn(a.x, a.y);
    __half2 h1 = __floats2half2_rn(a.z, a.w);
    __half2 h2 = __floats2half2_rn(c.x, c.y);
    __half2 h3 = __floats2half2_rn(c.z, c.w);
    uint4 o;
    o.x = *(uint32_t*)&h0; o.y = *(uint32_t*)&h1;
    o.z = *(uint32_t*)&h2; o.w = *(uint32_t*)&h3;
    *(uint4*)(&g_xh[(size_t)blockIdx.x * 2048 + threadIdx.x * 8]) = o;
}

__global__ void k_edgecast(const int* __restrict__ ei, float* __restrict__ outTail) {
    int i = blockIdx.x * 4096 + threadIdx.x * 4;
    if (i < 2 * N_EDGES) {
        int4 v = *(const int4*)(ei + i);
        *(float4*)(outTail + i) = make_float4((float)v.x, (float)v.y,
                                              (float)v.z, (float)v.w);
    }
}

// ---------------- CSR build ----------------
__global__ void k_hist(const int* __restrict__ ei) {
    int e = blockIdx.x * blockDim.x + threadIdx.x;
    if (e < N_EDGES) atomicAdd(&g_deg[ei[N_EDGES + e]], 1);
}
__global__ void k_scan() {
    __shared__ int ss[1024];
    int t = threadIdx.x;
    const int CH = (N_NODES + 1023) / 1024;
    int b0 = t * CH, b1 = min(b0 + CH, N_NODES);
    int s = 0;
    for (int i = b0; i < b1; i++) s += g_deg[i];
    ss[t] = s; __syncthreads();
    for (int off = 1; off < 1024; off <<= 1) {
        int v = (t >= off) ? ss[t - off] : 0;
        __syncthreads(); ss[t] += v; __syncthreads();
    }
    int excl = (t == 0) ? 0 : ss[t - 1];
    for (int i = b0; i < b1; i++) { g_rowptr[i] = excl; excl += g_deg[i]; }
    if (t == 1023) g_rowptr[N_NODES] = excl;
}
__global__ void k_fill(const int* __restrict__ ei) {
    int e = (blockIdx.x * blockDim.x + threadIdx.x) * 2;
    if (e < N_EDGES) {
        int dst0 = ei[N_EDGES + e];
        int src0 = ei[e];
        int dst1 = (e + 1 < N_EDGES) ? ei[N_EDGES + e + 1] : -1;
        int src1 = (e + 1 < N_EDGES) ? ei[e + 1] : 0;
        int p0 = atomicAdd(&g_fill[dst0], 1);
        g_csr_src[g_rowptr[dst0] + p0] = src0;
        if (dst1 >= 0) {
            int p1 = atomicAdd(&g_fill[dst1], 1);
            g_csr_src[g_rowptr[dst1] + p1] = src1;
        }
    }
}

// ---------------- mean aggregation: warp/node, half-warp edge pairing ----------
// 16 lanes x LDG.128 cover one 256B row; half 0 = even edges, half 1 = odd.
__device__ __forceinline__ void add8(float* acc, uint4 v) {
    float2 f;
    f = __half22float2(*(__half2*)&v.x); acc[0] += f.x; acc[1] += f.y;
    f = __half22float2(*(((__half2*)&v.x) + 1)); acc[2] += f.x; acc[3] += f.y;
    f = __half22float2(*(__half2*)&v.z); acc[4] += f.x; acc[5] += f.y;
    f = __half22float2(*(((__half2*)&v.z) + 1)); acc[6] += f.x; acc[7] += f.y;
}

template <int LAYER>
__global__ void k_agg() {
    const uint4* __restrict__ xin =
        (const uint4*)((LAYER == 1) ? g_xh : g_hh);   // 16 uint4 per row
    int gw = (blockIdx.x * blockDim.x + threadIdx.x) >> 5;
    int lane = threadIdx.x & 31;
    int half = lane >> 4, sl = lane & 15;
    if (gw >= N_NODES) return;
    int e0 = g_rowptr[gw], e1 = g_rowptr[gw + 1];
    float acc[8] = {0.f, 0.f, 0.f, 0.f, 0.f, 0.f, 0.f, 0.f};
    int e = e0 + half;
    for (; e + 6 < e1; e += 8) {
        int s0 = g_csr_src[e],     s1 = g_csr_src[e + 2];
        int s2 = g_csr_src[e + 4], s3 = g_csr_src[e + 6];
        uint4 v0 = xin[(size_t)s0 * 16 + sl];
        uint4 v1 = xin[(size_t)s1 * 16 + sl];
        uint4 v2 = xin[(size_t)s2 * 16 + sl];
        uint4 v3 = xin[(size_t)s3 * 16 + sl];
        add8(acc, v0); add8(acc, v1); add8(acc, v2); add8(acc, v3);
    }
    for (; e < e1; e += 2) {
        int s = g_csr_src[e];
        uint4 v = xin[(size_t)s * 16 + sl];
        add8(acc, v);
    }
    // merge odd-edge half into even half (lane i += lane i+16)
#pragma unroll
    for (int j = 0; j < 8; j++)
        acc[j] += __shfl_down_sync(0xFFFFFFFFu, acc[j], 16);
    if (half == 0) {
        int d = e1 - e0;
        float di = (d > 0) ? (1.0f / (float)d) : 0.0f;
        __half2 p0 = __floats2half2_rn(acc[0] * di, acc[1] * di);
        __half2 p1 = __floats2half2_rn(acc[2] * di, acc[3] * di);
        __half2 p2 = __floats2half2_rn(acc[4] * di, acc[5] * di);
        __half2 p3 = __floats2half2_rn(acc[6] * di, acc[7] * di);
        uint4 o;
        o.x = *(uint32_t*)&p0; o.y = *(uint32_t*)&p1;
        o.z = *(uint32_t*)&p2; o.w = *(uint32_t*)&p3;
        *(uint4*)(&g_aggh[(size_t)gw * D + sl * 8]) = o;
    }
}

// ---------------- WMMA fp16 single-term fused SAGE linear ----------------
// out[128x128] = agg@Wl + root@Wr + bias (+ReLU layer1); A,B plain fp16.
#define LDA 136
#define LDB 136
#define LDC 132
#define SM_BIAS   (16 * 136 * 4)                 /* 8704 */
#define SM_TILE   (128 * 136 * 2)                /* 34816 */
#define SMEM_REQ  (SM_BIAS + 2 * SM_TILE)        /* 78336 */

template <int LAYER>
__global__ void __launch_bounds__(256, 2) k_wgemm(
    const float* __restrict__ bias,
    float* __restrict__ OutExt)
{
    extern __shared__ char smem[];
    float* bias_rep = (float*)smem;
    __half* As = (__half*)(smem + SM_BIAS);
    __half* Bs = As + 128 * LDA;

    const int tid = threadIdx.x;
    const int wid = tid >> 5;
    const int row0 = blockIdx.x * 128;
    const int wy = wid >> 1;
    const int wx = wid & 1;

    for (int i = tid; i < 16 * 128; i += 256) {
        int r = i >> 7, c = i & 127;
        bias_rep[r * 136 + c] = bias[c];
    }
    __syncthreads();

    wmma::fragment<wmma::accumulator, 16, 16, 16, float> acc[2][4];
#pragma unroll
    for (int i = 0; i < 2; i++)
#pragma unroll
        for (int j = 0; j < 4; j++)
            wmma::load_matrix_sync(acc[i][j], bias_rep + wx * 64 + j * 16, 136,
                                   wmma::mem_row_major);

    const int wl = (LAYER == 1) ? 0 : 2;
#pragma unroll 1
    for (int side = 0; side < 2; side++) {
        if (side == 1) __syncthreads();
        const __half* __restrict__ Asrc =
            (side == 0) ? g_aggh : ((LAYER == 1) ? g_xh : g_hh);
        const uint4* av = (const uint4*)(Asrc + (size_t)row0 * D);
        const uint4* bv = (const uint4*)&g_Wimg[wl + side][0];
#pragma unroll
        for (int it = 0; it < 8; it++) {
            int idx = tid + it * 256;            // 2048 uint4 (8 halves each)
            int m = idx >> 4, c = idx & 15;
            *(uint4*)&As[m * LDA + c * 8] = av[idx];
            *(uint4*)&Bs[m * LDB + c * 8] = bv[idx];
        }
        __syncthreads();

#pragma unroll
        for (int ks = 0; ks < 8; ks++) {
            int k0 = ks * 16;
            wmma::fragment<wmma::matrix_a, 16, 16, 16, __half, wmma::row_major> a[2];
#pragma unroll
            for (int i = 0; i < 2; i++)
                wmma::load_matrix_sync(a[i], As + (wy * 32 + i * 16) * LDA + k0, LDA);
#pragma unroll
            for (int j = 0; j < 4; j++) {
                int n0 = wx * 64 + j * 16;
                wmma::fragment<wmma::matrix_b, 16, 16, 16, __half, wmma::row_major> b;
                wmma::load_matrix_sync(b, Bs + k0 * LDB + n0, LDB);
#pragma unroll
                for (int i = 0; i < 2; i++)
                    wmma::mma_sync(acc[i][j], a[i], b, acc[i][j]);
            }
        }
    }

    // ---- epilogue ----
    if (LAYER == 1) {
#pragma unroll
        for (int i = 0; i < 2; i++)
#pragma unroll
            for (int j = 0; j < 4; j++)
#pragma unroll
                for (int t = 0; t < acc[i][j].num_elements; t++)
                    acc[i][j].x[t] = fmaxf(acc[i][j].x[t], 0.f);
        float* bounce = (float*)smem;
        __syncthreads();
#pragma unroll
        for (int i = 0; i < 2; i++)
#pragma unroll
            for (int j = 0; j < 4; j++)
                wmma::store_matrix_sync(
                    bounce + (size_t)(wy * 32 + i * 16) * LDC + wx * 64 + j * 16,
                    acc[i][j], LDC, wmma::mem_row_major);
        __syncthreads();
        for (int idx = tid; idx < 128 * 32; idx += 256) {
            int r = idx >> 5, q = idx & 31;
            float4 v = *(float4*)&bounce[r * LDC + q * 4];
            __half2 p0 = __floats2half2_rn(v.x, v.y);
            __half2 p1 = __floats2half2_rn(v.z, v.w);
            uint2 hv;
            hv.x = *(uint32_t*)&p0; hv.y = *(uint32_t*)&p1;
            *(uint2*)(&g_hh[(size_t)(row0 + r) * D + q * 4]) = hv;
        }
        return;
    }

    bool direct = (row0 + 128 <= N_NODES);
    if (direct) {
#pragma unroll
        for (int i = 0; i < 2; i++)
#pragma unroll
            for (int j = 0; j < 4; j++)
                wmma::store_matrix_sync(
                    OutExt + (size_t)(row0 + wy * 32 + i * 16) * D + wx * 64 + j * 16,
                    acc[i][j], D, wmma::mem_row_major);
    } else {
        float* bounce = (float*)smem;
        __syncthreads();
#pragma unroll
        for (int i = 0; i < 2; i++)
#pragma unroll
            for (int j = 0; j < 4; j++)
                wmma::store_matrix_sync(
                    bounce + (size_t)(wy * 32 + i * 16) * LDC + wx * 64 + j * 16,
                    acc[i][j], LDC, wmma::mem_row_major);
        __syncthreads();
        int valid = N_NODES - row0;
        for (int idx = tid; idx < valid * 32; idx += 256) {
            int r = idx >> 5, q = idx & 31;
            float4 v = *(float4*)&bounce[r * LDC + q * 4];
            *(float4*)(OutExt + (size_t)(row0 + r) * D + q * 4) = v;
        }
    }
}

// ---------------- launch (3 parallel graph branches) ----------------
extern "C" void kernel_launch(void* const* d_in, const int* in_sizes, int n_in,
                              void* d_out, int out_size)
{
    const float* x   = (const float*)d_in[0];
    const float* W1l = (const float*)d_in[1];
    const float* b1  = (const float*)d_in[2];
    const float* W1r = (const float*)d_in[3];
    const float* W2l = (const float*)d_in[4];
    const float* b2  = (const float*)d_in[5];
    const float* W2r = (const float*)d_in[6];
    const int*   ei  = (const int*)d_in[7];
    float* out = (float*)d_out;

    static cudaStream_t s1 = nullptr, s2 = nullptr;
    static cudaEvent_t evRoot = nullptr, evPrep = nullptr, evEdge = nullptr;
    if (!s1) {
        cudaStreamCreateWithFlags(&s1, cudaStreamNonBlocking);
        cudaStreamCreateWithFlags(&s2, cudaStreamNonBlocking);
        cudaEventCreateWithFlags(&evRoot, cudaEventDisableTiming);
        cudaEventCreateWithFlags(&evPrep, cudaEventDisableTiming);
        cudaEventCreateWithFlags(&evEdge, cudaEventDisableTiming);
        cudaFuncSetAttribute(k_wgemm<1>, cudaFuncAttributeMaxDynamicSharedMemorySize, SMEM_REQ);
        cudaFuncSetAttribute(k_wgemm<2>, cudaFuncAttributeMaxDynamicSharedMemorySize, SMEM_REQ);
    }

    const int TB = 256;
    const int aggBlocks  = (N_NODES * 32 + TB - 1) / TB;
    const int gemmBlocks = (N_NODES + 127) / 128;   // 782

    // fork
    cudaEventRecord(evRoot, 0);
    cudaStreamWaitEvent(s1, evRoot, 0);
    cudaStreamWaitEvent(s2, evRoot, 0);

    // branch s1: weight prep + x->fp16 (needed by agg1/gemm1)
    k_wprep<<<4, TB, 0, s1>>>(W1l, W1r, W2l, W2r);
    k_xconv<<<6250, TB, 0, s1>>>(x);
    cudaEventRecord(evPrep, s1);

    // branch s2: edge_index passthrough cast (independent)
    k_edgecast<<<782, 1024, 0, s2>>>(ei, out + (size_t)N_NODES * D);
    cudaEventRecord(evEdge, s2);

    // branch s0: CSR build chain
    k_zero<<<(N_NODES + TB - 1) / TB, TB>>>();
    k_hist<<<(N_EDGES + TB - 1) / TB, TB>>>(ei);
    k_scan<<<1, 1024>>>();
    k_fill<<<(N_EDGES / 2 + TB - 1) / TB, TB>>>(ei);

    // join prep branch, then compute
    cudaStreamWaitEvent(0, evPrep, 0);
    k_agg<1><<<aggBlocks, TB>>>();
    k_wgemm<1><<<gemmBlocks, TB, SMEM_REQ>>>(b1, nullptr);
    k_agg<2><<<aggBlocks, TB>>>();
    k_wgemm<2><<<gemmBlocks, TB, SMEM_REQ>>>(b2, out);

    // join edgecast branch
    cudaStreamWaitEvent(0, evEdge, 0);
}